// round 10
// baseline (speedup 1.0000x reference)
#include <cuda_runtime.h>
#include <stdint.h>
#include <math.h>

#define NE 320000
#define NA 10000
#define CAP 128            // per-atom bin capacity (P(deg>128) ~ e^-81)
#define RCV 5.0f
#define TBL_N 512
#define PIF 3.14159265358979323846f
#define EDGE_BLOCKS (NE / 128)     // 2500
#define TBL_BLOCKS 257             // 2 rows per block -> 514 >= 513

// ---- scratch (device globals; zero-initialized at load; no runtime allocation) ----
__device__ float g_pre[(size_t)NA * CAP * 40];  // per edge (binned): comps[35], u, sj[4]
__device__ float g_tbl[(TBL_N + 1) * 64];       // layout [idx][r][8]: val(8k+r) at idx*64+r*8+k
__device__ int   g_cursor[NA];                  // starts 0; k_atom_mlp resets to 0 each call
__device__ int   g_work;                        // work-stealing counter; k_edge resets

__device__ __forceinline__ float silu(float x) { return x / (1.0f + __expf(-x)); }

__device__ __forceinline__ void cp16(unsigned int s, const void* g) {
    asm volatile("cp.async.cg.shared.global [%0], [%1], 16;" :: "r"(s), "l"(g));
}
#define CP_COMMIT() asm volatile("cp.async.commit_group;")
#define CP_WAIT(n)  asm volatile("cp.async.wait_group %0;" :: "n"(n))

// ---- pass 1: edge blocks (0..2499) + table blocks (2500..2756) in one grid ----
__global__ __launch_bounds__(128) void k_edge_tbl(
    const float* __restrict__ rij, const int* __restrict__ species,
    const int* __restrict__ fa, const int* __restrict__ sa,
    const float* __restrict__ Wr1, const float* __restrict__ br1,
    const float* __restrict__ Wr2, const float* __restrict__ br2,
    const float* __restrict__ Ws1, const float* __restrict__ bs1,
    const float* __restrict__ Ws2, const float* __restrict__ bs2)
{
    int t = threadIdx.x;

    if (blockIdx.x >= EDGE_BLOCKS) {
        if (blockIdx.x == EDGE_BLOCKS && t == 0) g_work = 0;   // reset stealer
        // ---- table build: 2 rows per block, 64 threads per row ----
        __shared__ float sh[2][64];
        int b = blockIdx.x - EDGE_BLOCKS;
        int half = t >> 6, i = t & 63;
        int idx = b * 2 + half;
        bool ok = (idx <= TBL_N);
        float fc = 0.f, h = 0.f;
        if (ok) {
            float d = idx * (RCV / TBL_N);
            float dd = fmaxf(d, 1e-6f);
            fc = 0.5f * (cosf(PIF * d * (1.0f / RCV)) + 1.0f);
            float a1 = PIF * dd * (1.0f / RCV);
            float s1, c1;
            sincosf(a1, &s1, &c1);
            float pref = sqrtf(2.0f / RCV) / dd;
            float bes[8];
            float prev = 0.0f, cur = s1, twoc = 2.0f * c1;
            bes[0] = cur * pref;
#pragma unroll
            for (int k = 1; k < 8; k++) { float nxt = twoc * cur - prev; bes[k] = nxt * pref; prev = cur; cur = nxt; }
            h = br1[i];
#pragma unroll
            for (int k = 0; k < 8; k++) h = fmaf(bes[k], __ldg(&Wr1[k * 64 + i]), h);
            h = silu(h);
        }
        sh[half][i] = h;
        __syncthreads();
        if (ok && i < 48) {
            float acc = br2[i];
            const float* hh = sh[half];
#pragma unroll 8
            for (int k = 0; k < 64; k++) acc = fmaf(hh[k], __ldg(&Wr2[k * 48 + i]), acc);
            // layout [idx][r][8]: output j=8k+r -> idx*64 + (j&7)*8 + (j>>3)
            g_tbl[(size_t)idx * 64 + (i & 7) * 8 + (i >> 3)] = silu(acc) * fc;
        }
        return;
    }

    // ---- edge path ----
    __shared__ float buf[4][40 * 33];   // per-warp transpose buffer, padded stride
    __shared__ int   sp[4][32];
    __shared__ float sem[4][12];        // per-warp species embedding table

    int warp = t >> 5, lane = t & 31;
    int e = blockIdx.x * 128 + t;

    // species embedding computed inline (3 species x 4 outputs; lanes 0..11)
    if (lane < 12) {
        int spq = lane >> 2, so = lane & 3;
        float a = bs2[so];
#pragma unroll
        for (int i = 0; i < 16; i++)
            a = fmaf(tanhf(Ws1[spq * 16 + i] + bs1[i]), Ws2[i * 4 + so], a);
        sem[warp][lane] = a;
    }

    float x = rij[3 * e + 0], y = rij[3 * e + 1], z = rij[3 * e + 2];
    float d = sqrtf(x * x + y * y + z * z + 1e-12f);
    float inv = 1.0f / d;
    float hx = x * inv, hy = y * inv, hz = z * inv;
    float u = d * ((float)TBL_N / RCV);

    int a = fa[e];
    int row = a * CAP + atomicAdd(&g_cursor[a], 1);
    sp[warp][lane] = row;

    float px2 = hx * hx, px3 = px2 * hx, px4 = px2 * px2;
    float py2 = hy * hy, py3 = py2 * hy, py4 = py2 * py2;
    float pz2 = hz * hz, pz3 = pz2 * hz, pz4 = pz2 * pz2;
    const float PX[5] = {1.f, hx, px2, px3, px4};
    const float PY[5] = {1.f, hy, py2, py3, py4};
    const float PZ[5] = {1.f, hz, pz2, pz3, pz4};
    constexpr int PA[35] = {0, 0,0,1, 0,0,0,1,1,2, 0,0,0,0,1,1,1,2,2,3, 0,0,0,0,0,1,1,1,1,2,2,2,3,3,4};
    constexpr int PB[35] = {0, 0,1,0, 0,1,2,0,1,0, 0,1,2,3,0,1,2,0,1,0, 0,1,2,3,4,0,1,2,3,0,1,2,0,1,0};
    constexpr int PC[35] = {0, 1,0,0, 2,1,0,1,0,0, 3,2,1,0,2,1,0,1,0,0, 4,3,2,1,0,3,2,1,0,2,1,0,1,0,0};
    float* bb = buf[warp];
#pragma unroll
    for (int c = 0; c < 35; c++) bb[c * 33 + lane] = PX[PA[c]] * PY[PB[c]] * PZ[PC[c]];
    bb[35 * 33 + lane] = u;
    __syncwarp();
    int spc = species[sa[e]];
#pragma unroll
    for (int s = 0; s < 4; s++) bb[(36 + s) * 33 + lane] = sem[warp][spc * 4 + s];
    __syncwarp();

    for (int k = lane; k < 32 * 40; k += 32) {
        int el = k / 40, j = k - el * 40;
        g_pre[(size_t)sp[warp][el] * 40 + j] = bb[j * 33 + el];
    }
}

// ---- pass 2: persistent work-stealing warps; 8-slot cp.async ring; fused MLP ----
__global__ __launch_bounds__(256) void k_atom_mlp(
    const float* __restrict__ Wa1, const float* __restrict__ ba1,
    const float* __restrict__ Wa2, const float* __restrict__ ba2,
    const float* __restrict__ Wa3, const float* __restrict__ ba3,
    float* __restrict__ out)
{
    const int D = 8;
    __shared__ __align__(16) float stage[8][D][40];
    __shared__ float sfeat[8][192];
    __shared__ float sh1[8][64];
    __shared__ float sW2[4096];
    __shared__ float sW3[64], sB1[64], sB2[64];

    int t = threadIdx.x, warp = t >> 5, lane = t & 31;
    for (int i = t; i < 4096; i += 256) sW2[i] = Wa2[i];
    if (t < 64) { sW3[t] = Wa3[t]; sB1[t] = ba1[t]; sB2[t] = ba2[t]; }
    __syncthreads();

    int r = lane & 7, s = lane >> 3;
    unsigned int sbase = (unsigned int)__cvta_generic_to_shared(&stage[warp][0][0]) + lane * 16;
    const float* tblr = g_tbl + r * 8;

    for (;;) {
        int n;
        if (lane == 0) n = atomicAdd(&g_work, 1);
        n = __shfl_sync(0xffffffffu, n, 0);
        if (n >= NA) break;

        int cnt = g_cursor[n];
        if (lane == 0) g_cursor[n] = 0;    // reset for next graph replay
        float acc[35];
#pragma unroll
        for (int c = 0; c < 35; c++) acc[c] = 0.f;
        float lin = 0.f;
        const float* base = g_pre + (size_t)n * CAP * 40;

        // prologue: commit exactly 4 groups (empty when j >= cnt)
#pragma unroll
        for (int j = 0; j < 4; j++) {
            if (j < cnt && lane < 10) cp16(sbase + j * 160, base + (size_t)j * 40 + lane * 4);
            CP_COMMIT();
        }

        float4 ca, cb; float2 ca2, cb2; float fr_cur = 0.f;
        if (cnt > 0) {
            CP_WAIT(2);
            __syncwarp();
            float u0 = stage[warp][0][35];
            int ir = (int)u0; ir = max(0, min(ir, TBL_N - 1));
            fr_cur = u0 - (float)ir;
            const float* t0 = tblr + (size_t)ir * 64;
            ca = *(const float4*)t0;  ca2 = *(const float2*)(t0 + 4);
            cb = *(const float4*)(t0 + 64); cb2 = *(const float2*)(t0 + 68);
        }

        for (int i = 0; i < cnt; i++) {
            CP_WAIT(2);                       // edges i and i+1 resident
            __syncwarp();
            const float* sb  = stage[warp][i & (D - 1)];
            const float* sb1 = stage[warp][(i + 1) & (D - 1)];
            float u_next = (i + 1 < cnt) ? sb1[35] : 0.f;
            int irn = (int)u_next; irn = max(0, min(irn, TBL_N - 1));
            float fr_next = u_next - (float)irn;
            const float* tn = tblr + (size_t)irn * 64;
            float4 na = *(const float4*)tn;  float2 na2 = *(const float2*)(tn + 4);
            float4 nb = *(const float4*)(tn + 64); float2 nb2 = *(const float2*)(tn + 68);

            float F0 = fmaf(fr_cur, cb.x - ca.x, ca.x);
            float F1 = fmaf(fr_cur, cb.y - ca.y, ca.y);
            float F2 = fmaf(fr_cur, cb.z - ca.z, ca.z);
            float F3 = fmaf(fr_cur, cb.w - ca.w, ca.w);
            float F4 = fmaf(fr_cur, cb2.x - ca2.x, ca2.x);
            float F5 = fmaf(fr_cur, cb2.y - ca2.y, ca2.y);
            float sj = sb[36 + s];
            lin = fmaf(F0, sj, lin);
            float m0 = F1 * sj, m1 = F2 * sj, m2 = F3 * sj, m3 = F4 * sj, m4 = F5 * sj;
            const float4* cp = (const float4*)sb;
            float4 q0 = cp[0], q1 = cp[1], q2 = cp[2], q3 = cp[3], q4 = cp[4],
                   q5 = cp[5], q6 = cp[6], q7 = cp[7], q8 = cp[8];
            acc[0]  = fmaf(m0, q0.x, acc[0]);
            acc[1]  = fmaf(m1, q0.y, acc[1]);  acc[2]  = fmaf(m1, q0.z, acc[2]);  acc[3]  = fmaf(m1, q0.w, acc[3]);
            acc[4]  = fmaf(m2, q1.x, acc[4]);  acc[5]  = fmaf(m2, q1.y, acc[5]);  acc[6]  = fmaf(m2, q1.z, acc[6]);
            acc[7]  = fmaf(m2, q1.w, acc[7]);  acc[8]  = fmaf(m2, q2.x, acc[8]);  acc[9]  = fmaf(m2, q2.y, acc[9]);
            acc[10] = fmaf(m3, q2.z, acc[10]); acc[11] = fmaf(m3, q2.w, acc[11]);
            acc[12] = fmaf(m3, q3.x, acc[12]); acc[13] = fmaf(m3, q3.y, acc[13]);
            acc[14] = fmaf(m3, q3.z, acc[14]); acc[15] = fmaf(m3, q3.w, acc[15]);
            acc[16] = fmaf(m3, q4.x, acc[16]); acc[17] = fmaf(m3, q4.y, acc[17]);
            acc[18] = fmaf(m3, q4.z, acc[18]); acc[19] = fmaf(m3, q4.w, acc[19]);
            acc[20] = fmaf(m4, q5.x, acc[20]); acc[21] = fmaf(m4, q5.y, acc[21]);
            acc[22] = fmaf(m4, q5.z, acc[22]); acc[23] = fmaf(m4, q5.w, acc[23]);
            acc[24] = fmaf(m4, q6.x, acc[24]); acc[25] = fmaf(m4, q6.y, acc[25]);
            acc[26] = fmaf(m4, q6.z, acc[26]); acc[27] = fmaf(m4, q6.w, acc[27]);
            acc[28] = fmaf(m4, q7.x, acc[28]); acc[29] = fmaf(m4, q7.y, acc[29]);
            acc[30] = fmaf(m4, q7.z, acc[30]); acc[31] = fmaf(m4, q7.w, acc[31]);
            acc[32] = fmaf(m4, q8.x, acc[32]); acc[33] = fmaf(m4, q8.y, acc[33]);
            acc[34] = fmaf(m4, q8.z, acc[34]);
            // refill slot (i+4)&7 (holds edge i-4, consumed; ordered by post-wait syncwarps)
            if (i + 4 < cnt && lane < 10)
                cp16(sbase + ((i + 4) & (D - 1)) * 160, base + (size_t)(i + 4) * 40 + lane * 4);
            CP_COMMIT();
            fr_cur = fr_next; ca = na; ca2 = na2; cb = nb; cb2 = nb2;
        }
        CP_WAIT(0);
        __syncwarp();

        // contract squared moments into feat[192] (per-warp smem)
        float* sf = sfeat[warp];
        sf[r * 4 + s] = lin;
        sf[(8 + r) * 4 + s] = acc[0] * acc[0];
        sf[(16 + r) * 4 + s] = acc[1] * acc[1] + acc[2] * acc[2] + acc[3] * acc[3];
        sf[(24 + r) * 4 + s] = acc[4] * acc[4] + 2.f * acc[5] * acc[5] + acc[6] * acc[6]
                             + 2.f * acc[7] * acc[7] + 2.f * acc[8] * acc[8] + acc[9] * acc[9];
        const float nm3[10] = {1, 3, 3, 1, 3, 6, 3, 3, 3, 1};
        float f3 = 0.f;
#pragma unroll
        for (int c = 0; c < 10; c++) f3 += nm3[c] * acc[10 + c] * acc[10 + c];
        sf[(32 + r) * 4 + s] = f3;
        const float nm4[15] = {1, 4, 6, 4, 1, 4, 12, 12, 4, 6, 12, 6, 4, 4, 1};
        float f4 = 0.f;
#pragma unroll
        for (int c = 0; c < 15; c++) f4 += nm4[c] * acc[20 + c] * acc[20 + c];
        sf[(40 + r) * 4 + s] = f4;
        __syncwarp();

        // per-warp MLP: 192 -> 64 -> 64 -> 1
        float h0 = sB1[2 * lane], h1 = sB1[2 * lane + 1];
        const float2* W1 = (const float2*)Wa1;
#pragma unroll 4
        for (int f = 0; f < 192; f++) {
            float fv = sf[f];
            float2 w = __ldg(&W1[f * 32 + lane]);
            h0 += fv * w.x; h1 += fv * w.y;
        }
        h0 = silu(h0); h1 = silu(h1);
        ((float2*)sh1[warp])[lane] = make_float2(h0, h1);
        __syncwarp();

        float g0 = sB2[2 * lane], g1 = sB2[2 * lane + 1];
        const float2* W2 = (const float2*)sW2;
#pragma unroll 4
        for (int k = 0; k < 64; k++) {
            float hv = sh1[warp][k];
            float2 w = W2[k * 32 + lane];
            g0 += hv * w.x; g1 += hv * w.y;
        }
        g0 = silu(g0); g1 = silu(g1);
        float o = g0 * sW3[2 * lane] + g1 * sW3[2 * lane + 1];
#pragma unroll
        for (int off = 16; off; off >>= 1) o += __shfl_down_sync(0xffffffffu, o, off);
        if (lane == 0) out[n] = o + ba3[0];
    }
}

extern "C" void kernel_launch(void* const* d_in, const int* in_sizes, int n_in,
                              void* d_out, int out_size) {
    const float* rij = (const float*)d_in[0];
    const int* species = (const int*)d_in[1];
    const int* fa = (const int*)d_in[2];
    const int* sa = (const int*)d_in[3];
    const float* Wr1 = (const float*)d_in[4];
    const float* br1 = (const float*)d_in[5];
    const float* Wr2 = (const float*)d_in[6];
    const float* br2 = (const float*)d_in[7];
    const float* Ws1 = (const float*)d_in[8];
    const float* bs1 = (const float*)d_in[9];
    const float* Ws2 = (const float*)d_in[10];
    const float* bs2 = (const float*)d_in[11];
    const float* Wa1 = (const float*)d_in[12];
    const float* ba1 = (const float*)d_in[13];
    const float* Wa2 = (const float*)d_in[14];
    const float* ba2 = (const float*)d_in[15];
    const float* Wa3 = (const float*)d_in[16];
    const float* ba3 = (const float*)d_in[17];
    float* out = (float*)d_out;

    k_edge_tbl<<<EDGE_BLOCKS + TBL_BLOCKS, 128>>>(rij, species, fa, sa,
                                                  Wr1, br1, Wr2, br2,
                                                  Ws1, bs1, Ws2, bs2);
    k_atom_mlp<<<444, 256>>>(Wa1, ba1, Wa2, ba2, Wa3, ba3, out);
}

// round 11
// speedup vs baseline: 1.3643x; 1.3643x over previous
#include <cuda_runtime.h>
#include <stdint.h>
#include <math.h>

#define NE 320000
#define NA 10000
#define CAP 128            // per-atom bin capacity (P(deg>128) ~ e^-81)
#define RCV 5.0f
#define TBL_N 512
#define PIF 3.14159265358979323846f
#define EDGE_BLOCKS (NE / 128)     // 2500
#define TBL_BLOCKS 257             // 2 rows per block -> 514 >= 513

// ---- scratch (device globals; zero-initialized at load; no runtime allocation) ----
__device__ float4 g_pre[(size_t)NA * CAP];      // per edge (binned): hx,hy,hz, u+1024*spc
__device__ float  g_tbl[(TBL_N + 1) * 64];      // layout [idx][r][8]: val(8k+r) at idx*64+r*8+k
__device__ int    g_cursor[NA];                 // starts 0; k_atom_mlp resets to 0 each call

__device__ __forceinline__ float silu(float x) { return x / (1.0f + __expf(-x)); }

// ---- pass 1: edge blocks (0..2499) + table blocks (2500..2756) in one grid ----
__global__ __launch_bounds__(128) void k_edge_tbl(
    const float* __restrict__ rij, const int* __restrict__ species,
    const int* __restrict__ fa, const int* __restrict__ sa,
    const float* __restrict__ Wr1, const float* __restrict__ br1,
    const float* __restrict__ Wr2, const float* __restrict__ br2)
{
    int t = threadIdx.x;

    if (blockIdx.x >= EDGE_BLOCKS) {
        // ---- table build: 2 rows per block, 64 threads per row ----
        __shared__ float sh[2][64];
        int b = blockIdx.x - EDGE_BLOCKS;
        int half = t >> 6, i = t & 63;
        int idx = b * 2 + half;
        bool ok = (idx <= TBL_N);
        float fc = 0.f, h = 0.f;
        if (ok) {
            float d = idx * (RCV / TBL_N);
            float dd = fmaxf(d, 1e-6f);
            fc = 0.5f * (cosf(PIF * d * (1.0f / RCV)) + 1.0f);
            float a1 = PIF * dd * (1.0f / RCV);
            float s1, c1;
            sincosf(a1, &s1, &c1);
            float pref = sqrtf(2.0f / RCV) / dd;
            float bes[8];
            float prev = 0.0f, cur = s1, twoc = 2.0f * c1;
            bes[0] = cur * pref;
#pragma unroll
            for (int k = 1; k < 8; k++) { float nxt = twoc * cur - prev; bes[k] = nxt * pref; prev = cur; cur = nxt; }
            h = br1[i];
#pragma unroll
            for (int k = 0; k < 8; k++) h = fmaf(bes[k], __ldg(&Wr1[k * 64 + i]), h);
            h = silu(h);
        }
        sh[half][i] = h;
        __syncthreads();
        if (ok && i < 48) {
            float acc = br2[i];
            const float* hh = sh[half];
#pragma unroll 8
            for (int k = 0; k < 64; k++) acc = fmaf(hh[k], __ldg(&Wr2[k * 48 + i]), acc);
            // layout [idx][r][8]: output j=8k+r -> idx*64 + (j&7)*8 + (j>>3)
            g_tbl[(size_t)idx * 64 + (i & 7) * 8 + (i >> 3)] = silu(acc) * fc;
        }
        return;
    }

    // ---- edge path: 16B payload, no transpose needed ----
    int e = blockIdx.x * 128 + t;
    float x = rij[3 * e + 0], y = rij[3 * e + 1], z = rij[3 * e + 2];
    float d = sqrtf(x * x + y * y + z * z + 1e-12f);
    float inv = 1.0f / d;
    float u = d * ((float)TBL_N / RCV);
    int spc = species[sa[e]];
    float w = u + 1024.0f * (float)spc;
    int a = fa[e];
    int row = a * CAP + atomicAdd(&g_cursor[a], 1);
    g_pre[row] = make_float4(x * inv, y * inv, z * inv, w);
}

// ---- pass 2: warp-per-atom; register prefetch of 16B rows; fused MLP ----
__global__ __launch_bounds__(256) void k_atom_mlp(
    const float* __restrict__ Wa1, const float* __restrict__ ba1,
    const float* __restrict__ Wa2, const float* __restrict__ ba2,
    const float* __restrict__ Wa3, const float* __restrict__ ba3,
    const float* __restrict__ Ws1, const float* __restrict__ bs1,
    const float* __restrict__ Ws2, const float* __restrict__ bs2,
    float* __restrict__ out)
{
    __shared__ float sfeat[8][192];
    __shared__ float sh1[8][64];
    __shared__ float sW2[4096];
    __shared__ float sW3[64], sB1[64], sB2[64];
    __shared__ float sem[12];

    int t = threadIdx.x, warp = t >> 5, lane = t & 31;
    for (int i = t; i < 4096; i += 256) sW2[i] = Wa2[i];
    if (t < 64) { sW3[t] = Wa3[t]; sB1[t] = ba1[t]; sB2[t] = ba2[t]; }
    if (t < 12) {   // species embedding: 3 species x 4 outputs
        int spq = t >> 2, so = t & 3;
        float a = bs2[so];
#pragma unroll
        for (int i = 0; i < 16; i++)
            a = fmaf(tanhf(Ws1[spq * 16 + i] + bs1[i]), Ws2[i * 4 + so], a);
        sem[t] = a;
    }
    __syncthreads();

    int n = blockIdx.x * 8 + warp;           // grid is exactly NA/8
    int cnt = g_cursor[n];
    if (lane == 0) g_cursor[n] = 0;          // reset for next graph replay
    int r = lane & 7, s = lane >> 3;
    float acc[35];
#pragma unroll
    for (int c = 0; c < 35; c++) acc[c] = 0.f;
    float lin = 0.f;
    const float4* base = g_pre + (size_t)n * CAP;
    const float* tblr = g_tbl + r * 8;

    // depth-4 register prefetch (broadcast loads: all lanes same address)
    float4 va[4];
#pragma unroll
    for (int j = 0; j < 4; j++)
        va[j] = (j < cnt) ? __ldg(base + j) : make_float4(0.f, 0.f, 0.f, 0.f);

    float4 ta4, tb4; float2 ta2, tb2; float fr_cur = 0.f;
    if (cnt > 0) {
        float w0 = va[0].w;
        int sp0 = (int)(w0 * (1.0f / 1024.0f));
        float u0 = w0 - 1024.0f * (float)sp0;
        int ir = min((int)u0, TBL_N - 1);
        fr_cur = u0 - (float)ir;
        const float* t0 = tblr + ir * 64;
        ta4 = *(const float4*)t0;        ta2 = *(const float2*)(t0 + 4);
        tb4 = *(const float4*)(t0 + 64); tb2 = *(const float2*)(t0 + 68);
    }

    for (int i = 0; i < cnt; i++) {
        float4 p = va[i & 3];
        if (i + 4 < cnt) va[i & 3] = __ldg(base + i + 4);

        // radial values for current edge (consume table regs before reload)
        float F0 = fmaf(fr_cur, tb4.x - ta4.x, ta4.x);
        float F1 = fmaf(fr_cur, tb4.y - ta4.y, ta4.y);
        float F2 = fmaf(fr_cur, tb4.z - ta4.z, ta4.z);
        float F3 = fmaf(fr_cur, tb4.w - ta4.w, ta4.w);
        float F4 = fmaf(fr_cur, tb2.x - ta2.x, ta2.x);
        float F5 = fmaf(fr_cur, tb2.y - ta2.y, ta2.y);

        // sj for this edge/lane
        int spc = (int)(p.w * (1.0f / 1024.0f));
        float sj = sem[spc * 4 + s];

        // prefetch table row for edge i+1 (u decoded from resident register)
        if (i + 1 < cnt) {
            float w1 = va[(i + 1) & 3].w;
            int sp1 = (int)(w1 * (1.0f / 1024.0f));
            float u1 = w1 - 1024.0f * (float)sp1;
            int irn = min((int)u1, TBL_N - 1);
            fr_cur = u1 - (float)irn;
            const float* tn = tblr + irn * 64;
            ta4 = *(const float4*)tn;        ta2 = *(const float2*)(tn + 4);
            tb4 = *(const float4*)(tn + 64); tb2 = *(const float2*)(tn + 68);
        }

        float hx = p.x, hy = p.y, hz = p.z;
        lin = fmaf(F0, sj, lin);
        float m0 = F1 * sj, m1 = F2 * sj, m2 = F3 * sj, m3 = F4 * sj, m4 = F5 * sj;

        // monomial recursion (order matches reference term enumeration)
        float zz = hz * hz, yz = hy * hz, yy = hy * hy, xz = hx * hz, xy = hx * hy, xx = hx * hx;
        float z3 = hz * zz, yz2 = hy * zz, y2z = yy * hz, y3 = hy * yy,
              xz2 = hx * zz, xyz = hx * yz, xy2 = hx * yy, x2z = xx * hz, x2y = xx * hy, x3 = hx * xx;
        acc[0]  = fmaf(m0, 1.f, acc[0]);
        acc[1]  = fmaf(m1, hz, acc[1]);  acc[2]  = fmaf(m1, hy, acc[2]);  acc[3]  = fmaf(m1, hx, acc[3]);
        acc[4]  = fmaf(m2, zz, acc[4]);  acc[5]  = fmaf(m2, yz, acc[5]);  acc[6]  = fmaf(m2, yy, acc[6]);
        acc[7]  = fmaf(m2, xz, acc[7]);  acc[8]  = fmaf(m2, xy, acc[8]);  acc[9]  = fmaf(m2, xx, acc[9]);
        acc[10] = fmaf(m3, z3, acc[10]);  acc[11] = fmaf(m3, yz2, acc[11]);
        acc[12] = fmaf(m3, y2z, acc[12]); acc[13] = fmaf(m3, y3, acc[13]);
        acc[14] = fmaf(m3, xz2, acc[14]); acc[15] = fmaf(m3, xyz, acc[15]);
        acc[16] = fmaf(m3, xy2, acc[16]); acc[17] = fmaf(m3, x2z, acc[17]);
        acc[18] = fmaf(m3, x2y, acc[18]); acc[19] = fmaf(m3, x3, acc[19]);
        acc[20] = fmaf(m4, hz * z3, acc[20]);  acc[21] = fmaf(m4, hy * z3, acc[21]);
        acc[22] = fmaf(m4, yy * zz, acc[22]);  acc[23] = fmaf(m4, y3 * hz, acc[23]);
        acc[24] = fmaf(m4, hy * y3, acc[24]);  acc[25] = fmaf(m4, hx * z3, acc[25]);
        acc[26] = fmaf(m4, hx * yz2, acc[26]); acc[27] = fmaf(m4, hx * y2z, acc[27]);
        acc[28] = fmaf(m4, hx * y3, acc[28]);  acc[29] = fmaf(m4, xx * zz, acc[29]);
        acc[30] = fmaf(m4, xx * yz, acc[30]);  acc[31] = fmaf(m4, xx * yy, acc[31]);
        acc[32] = fmaf(m4, x3 * hz, acc[32]);  acc[33] = fmaf(m4, x3 * hy, acc[33]);
        acc[34] = fmaf(m4, hx * x3, acc[34]);
    }

    // contract squared moments into feat[192] (per-warp smem)
    float* sf = sfeat[warp];
    sf[r * 4 + s] = lin;
    sf[(8 + r) * 4 + s] = acc[0] * acc[0];
    sf[(16 + r) * 4 + s] = acc[1] * acc[1] + acc[2] * acc[2] + acc[3] * acc[3];
    sf[(24 + r) * 4 + s] = acc[4] * acc[4] + 2.f * acc[5] * acc[5] + acc[6] * acc[6]
                         + 2.f * acc[7] * acc[7] + 2.f * acc[8] * acc[8] + acc[9] * acc[9];
    const float nm3[10] = {1, 3, 3, 1, 3, 6, 3, 3, 3, 1};
    float f3 = 0.f;
#pragma unroll
    for (int c = 0; c < 10; c++) f3 += nm3[c] * acc[10 + c] * acc[10 + c];
    sf[(32 + r) * 4 + s] = f3;
    const float nm4[15] = {1, 4, 6, 4, 1, 4, 12, 12, 4, 6, 12, 6, 4, 4, 1};
    float f4 = 0.f;
#pragma unroll
    for (int c = 0; c < 15; c++) f4 += nm4[c] * acc[20 + c] * acc[20 + c];
    sf[(40 + r) * 4 + s] = f4;
    __syncwarp();

    // per-warp MLP: 192 -> 64 -> 64 -> 1
    float h0 = sB1[2 * lane], h1 = sB1[2 * lane + 1];
    const float2* W1 = (const float2*)Wa1;
#pragma unroll 4
    for (int f = 0; f < 192; f++) {
        float fv = sf[f];
        float2 w = __ldg(&W1[f * 32 + lane]);
        h0 += fv * w.x; h1 += fv * w.y;
    }
    h0 = silu(h0); h1 = silu(h1);
    ((float2*)sh1[warp])[lane] = make_float2(h0, h1);
    __syncwarp();

    float g0 = sB2[2 * lane], g1 = sB2[2 * lane + 1];
    const float2* W2 = (const float2*)sW2;
#pragma unroll 4
    for (int k = 0; k < 64; k++) {
        float hv = sh1[warp][k];
        float2 w = W2[k * 32 + lane];
        g0 += hv * w.x; g1 += hv * w.y;
    }
    g0 = silu(g0); g1 = silu(g1);
    float o = g0 * sW3[2 * lane] + g1 * sW3[2 * lane + 1];
#pragma unroll
    for (int off = 16; off; off >>= 1) o += __shfl_down_sync(0xffffffffu, o, off);
    if (lane == 0) out[n] = o + ba3[0];
}

extern "C" void kernel_launch(void* const* d_in, const int* in_sizes, int n_in,
                              void* d_out, int out_size) {
    const float* rij = (const float*)d_in[0];
    const int* species = (const int*)d_in[1];
    const int* fa = (const int*)d_in[2];
    const int* sa = (const int*)d_in[3];
    const float* Wr1 = (const float*)d_in[4];
    const float* br1 = (const float*)d_in[5];
    const float* Wr2 = (const float*)d_in[6];
    const float* br2 = (const float*)d_in[7];
    const float* Ws1 = (const float*)d_in[8];
    const float* bs1 = (const float*)d_in[9];
    const float* Ws2 = (const float*)d_in[10];
    const float* bs2 = (const float*)d_in[11];
    const float* Wa1 = (const float*)d_in[12];
    const float* ba1 = (const float*)d_in[13];
    const float* Wa2 = (const float*)d_in[14];
    const float* ba2 = (const float*)d_in[15];
    const float* Wa3 = (const float*)d_in[16];
    const float* ba3 = (const float*)d_in[17];
    float* out = (float*)d_out;

    k_edge_tbl<<<EDGE_BLOCKS + TBL_BLOCKS, 128>>>(rij, species, fa, sa,
                                                  Wr1, br1, Wr2, br2);
    k_atom_mlp<<<NA / 8, 256>>>(Wa1, ba1, Wa2, ba2, Wa3, ba3,
                                Ws1, bs1, Ws2, bs2, out);
}

// round 12
// speedup vs baseline: 1.3683x; 1.0029x over previous
#include <cuda_runtime.h>
#include <stdint.h>
#include <math.h>

#define NE 320000
#define NA 10000
#define CAP 128            // per-atom bin capacity (P(deg>128) ~ e^-81)
#define RCV 5.0f
#define TBL_N 512
#define PIF 3.14159265358979323846f
#define EDGE_BLOCKS (NE / 128)     // 2500
#define TBL_BLOCKS 257             // 2 rows per block -> 514 >= 513

// ---- scratch (device globals; zero-initialized at load; no runtime allocation) ----
__device__ float4 g_pre[(size_t)NA * CAP];      // per edge (binned): hx,hy,hz, u+1024*spc
__device__ float  g_tbl[(TBL_N + 1) * 64];      // layout [idx][r][8]: val(8k+r) at idx*64+r*8+k
__device__ int    g_cursor[NA];                 // starts 0; k_atom_mlp resets to 0 each call

__device__ __forceinline__ float silu(float x) { return x / (1.0f + __expf(-x)); }

// ---- pass 1: edge blocks (0..2499) + table blocks (2500..2756) in one grid ----
__global__ __launch_bounds__(128) void k_edge_tbl(
    const float* __restrict__ rij, const int* __restrict__ species,
    const int* __restrict__ fa, const int* __restrict__ sa,
    const float* __restrict__ Wr1, const float* __restrict__ br1,
    const float* __restrict__ Wr2, const float* __restrict__ br2)
{
    int t = threadIdx.x;

    if (blockIdx.x >= EDGE_BLOCKS) {
        // ---- table build: 2 rows per block, 64 threads per row ----
        __shared__ float sh[2][64];
        int b = blockIdx.x - EDGE_BLOCKS;
        int half = t >> 6, i = t & 63;
        int idx = b * 2 + half;
        bool ok = (idx <= TBL_N);
        float fc = 0.f, h = 0.f;
        if (ok) {
            float d = idx * (RCV / TBL_N);
            float dd = fmaxf(d, 1e-6f);
            fc = 0.5f * (cosf(PIF * d * (1.0f / RCV)) + 1.0f);
            float a1 = PIF * dd * (1.0f / RCV);
            float s1, c1;
            sincosf(a1, &s1, &c1);
            float pref = sqrtf(2.0f / RCV) / dd;
            float bes[8];
            float prev = 0.0f, cur = s1, twoc = 2.0f * c1;
            bes[0] = cur * pref;
#pragma unroll
            for (int k = 1; k < 8; k++) { float nxt = twoc * cur - prev; bes[k] = nxt * pref; prev = cur; cur = nxt; }
            h = br1[i];
#pragma unroll
            for (int k = 0; k < 8; k++) h = fmaf(bes[k], __ldg(&Wr1[k * 64 + i]), h);
            h = silu(h);
        }
        sh[half][i] = h;
        __syncthreads();
        if (ok && i < 48) {
            float acc = br2[i];
            const float* hh = sh[half];
#pragma unroll 8
            for (int k = 0; k < 64; k++) acc = fmaf(hh[k], __ldg(&Wr2[k * 48 + i]), acc);
            // layout [idx][r][8]: output j=8k+r -> idx*64 + (j&7)*8 + (j>>3)
            g_tbl[(size_t)idx * 64 + (i & 7) * 8 + (i >> 3)] = silu(acc) * fc;
        }
        return;
    }

    // ---- edge path: 16B payload, no transpose needed ----
    int e = blockIdx.x * 128 + t;
    float x = rij[3 * e + 0], y = rij[3 * e + 1], z = rij[3 * e + 2];
    float d = sqrtf(x * x + y * y + z * z + 1e-12f);
    float inv = 1.0f / d;
    float u = d * ((float)TBL_N / RCV);
    int spc = species[sa[e]];
    float w = u + 1024.0f * (float)spc;
    int a = fa[e];
    int row = a * CAP + atomicAdd(&g_cursor[a], 1);
    g_pre[row] = make_float4(x * inv, y * inv, z * inv, w);
}

// ---- pass 2: warp-per-atom accumulate; CTA-batched MLP ----
__global__ __launch_bounds__(256) void k_atom_mlp(
    const float* __restrict__ Wa1, const float* __restrict__ ba1,
    const float* __restrict__ Wa2, const float* __restrict__ ba2,
    const float* __restrict__ Wa3, const float* __restrict__ ba3,
    const float* __restrict__ Ws1, const float* __restrict__ bs1,
    const float* __restrict__ Ws2, const float* __restrict__ bs2,
    float* __restrict__ out)
{
    __shared__ __align__(16) float sfeat[8][192];
    __shared__ float sh1[8][64];
    __shared__ float sW2[4096];
    __shared__ float sW3[64], sB1[64], sB2[64];
    __shared__ float sem[12];
    __shared__ float spart[8][2];

    int t = threadIdx.x, warp = t >> 5, lane = t & 31;
    for (int i = t; i < 4096; i += 256) sW2[i] = Wa2[i];
    if (t < 64) { sW3[t] = Wa3[t]; sB1[t] = ba1[t]; sB2[t] = ba2[t]; }
    if (t < 12) {   // species embedding: 3 species x 4 outputs
        int spq = t >> 2, so = t & 3;
        float a = bs2[so];
#pragma unroll
        for (int i = 0; i < 16; i++)
            a = fmaf(tanhf(Ws1[spq * 16 + i] + bs1[i]), Ws2[i * 4 + so], a);
        sem[t] = a;
    }
    __syncthreads();

    int n = blockIdx.x * 8 + warp;           // grid is exactly NA/8
    int cnt = g_cursor[n];
    if (lane == 0) g_cursor[n] = 0;          // reset for next graph replay
    int r = lane & 7, s = lane >> 3;
    float acc[35];
#pragma unroll
    for (int c = 0; c < 35; c++) acc[c] = 0.f;
    float lin = 0.f;
    const float4* base = g_pre + (size_t)n * CAP;
    const float* tblr = g_tbl + r * 8;

    // depth-4 register prefetch (broadcast loads: all lanes same address)
    float4 va[4];
#pragma unroll
    for (int j = 0; j < 4; j++)
        va[j] = (j < cnt) ? __ldg(base + j) : make_float4(0.f, 0.f, 0.f, 0.f);

    float4 ta4, tb4; float2 ta2, tb2; float fr_cur = 0.f;
    if (cnt > 0) {
        float w0 = va[0].w;
        int sp0 = (int)(w0 * (1.0f / 1024.0f));
        float u0 = w0 - 1024.0f * (float)sp0;
        int ir = min((int)u0, TBL_N - 1);
        fr_cur = u0 - (float)ir;
        const float* t0 = tblr + ir * 64;
        ta4 = *(const float4*)t0;        ta2 = *(const float2*)(t0 + 4);
        tb4 = *(const float4*)(t0 + 64); tb2 = *(const float2*)(t0 + 68);
    }

    for (int i = 0; i < cnt; i++) {
        float4 p = va[i & 3];
        if (i + 4 < cnt) va[i & 3] = __ldg(base + i + 4);

        // radial values for current edge (consume table regs before reload)
        float F0 = fmaf(fr_cur, tb4.x - ta4.x, ta4.x);
        float F1 = fmaf(fr_cur, tb4.y - ta4.y, ta4.y);
        float F2 = fmaf(fr_cur, tb4.z - ta4.z, ta4.z);
        float F3 = fmaf(fr_cur, tb4.w - ta4.w, ta4.w);
        float F4 = fmaf(fr_cur, tb2.x - ta2.x, ta2.x);
        float F5 = fmaf(fr_cur, tb2.y - ta2.y, ta2.y);

        // sj for this edge/lane
        int spc = (int)(p.w * (1.0f / 1024.0f));
        float sj = sem[spc * 4 + s];

        // prefetch table row for edge i+1 (u decoded from resident register)
        if (i + 1 < cnt) {
            float w1 = va[(i + 1) & 3].w;
            int sp1 = (int)(w1 * (1.0f / 1024.0f));
            float u1 = w1 - 1024.0f * (float)sp1;
            int irn = min((int)u1, TBL_N - 1);
            fr_cur = u1 - (float)irn;
            const float* tn = tblr + irn * 64;
            ta4 = *(const float4*)tn;        ta2 = *(const float2*)(tn + 4);
            tb4 = *(const float4*)(tn + 64); tb2 = *(const float2*)(tn + 68);
        }

        float hx = p.x, hy = p.y, hz = p.z;
        lin = fmaf(F0, sj, lin);
        float m0 = F1 * sj, m1 = F2 * sj, m2 = F3 * sj, m3 = F4 * sj, m4 = F5 * sj;

        // monomial recursion (order matches reference term enumeration)
        float zz = hz * hz, yz = hy * hz, yy = hy * hy, xz = hx * hz, xy = hx * hy, xx = hx * hx;
        float z3 = hz * zz, yz2 = hy * zz, y2z = yy * hz, y3 = hy * yy,
              xz2 = hx * zz, xyz = hx * yz, xy2 = hx * yy, x2z = xx * hz, x2y = xx * hy, x3 = hx * xx;
        acc[0]  = fmaf(m0, 1.f, acc[0]);
        acc[1]  = fmaf(m1, hz, acc[1]);  acc[2]  = fmaf(m1, hy, acc[2]);  acc[3]  = fmaf(m1, hx, acc[3]);
        acc[4]  = fmaf(m2, zz, acc[4]);  acc[5]  = fmaf(m2, yz, acc[5]);  acc[6]  = fmaf(m2, yy, acc[6]);
        acc[7]  = fmaf(m2, xz, acc[7]);  acc[8]  = fmaf(m2, xy, acc[8]);  acc[9]  = fmaf(m2, xx, acc[9]);
        acc[10] = fmaf(m3, z3, acc[10]);  acc[11] = fmaf(m3, yz2, acc[11]);
        acc[12] = fmaf(m3, y2z, acc[12]); acc[13] = fmaf(m3, y3, acc[13]);
        acc[14] = fmaf(m3, xz2, acc[14]); acc[15] = fmaf(m3, xyz, acc[15]);
        acc[16] = fmaf(m3, xy2, acc[16]); acc[17] = fmaf(m3, x2z, acc[17]);
        acc[18] = fmaf(m3, x2y, acc[18]); acc[19] = fmaf(m3, x3, acc[19]);
        acc[20] = fmaf(m4, hz * z3, acc[20]);  acc[21] = fmaf(m4, hy * z3, acc[21]);
        acc[22] = fmaf(m4, yy * zz, acc[22]);  acc[23] = fmaf(m4, y3 * hz, acc[23]);
        acc[24] = fmaf(m4, hy * y3, acc[24]);  acc[25] = fmaf(m4, hx * z3, acc[25]);
        acc[26] = fmaf(m4, hx * yz2, acc[26]); acc[27] = fmaf(m4, hx * y2z, acc[27]);
        acc[28] = fmaf(m4, hx * y3, acc[28]);  acc[29] = fmaf(m4, xx * zz, acc[29]);
        acc[30] = fmaf(m4, xx * yz, acc[30]);  acc[31] = fmaf(m4, xx * yy, acc[31]);
        acc[32] = fmaf(m4, x3 * hz, acc[32]);  acc[33] = fmaf(m4, x3 * hy, acc[33]);
        acc[34] = fmaf(m4, hx * x3, acc[34]);
    }

    // contract squared moments into feat[192] (per-warp smem)
    float* sf = sfeat[warp];
    sf[r * 4 + s] = lin;
    sf[(8 + r) * 4 + s] = acc[0] * acc[0];
    sf[(16 + r) * 4 + s] = acc[1] * acc[1] + acc[2] * acc[2] + acc[3] * acc[3];
    sf[(24 + r) * 4 + s] = acc[4] * acc[4] + 2.f * acc[5] * acc[5] + acc[6] * acc[6]
                         + 2.f * acc[7] * acc[7] + 2.f * acc[8] * acc[8] + acc[9] * acc[9];
    const float nm3[10] = {1, 3, 3, 1, 3, 6, 3, 3, 3, 1};
    float f3 = 0.f;
#pragma unroll
    for (int c = 0; c < 10; c++) f3 += nm3[c] * acc[10 + c] * acc[10 + c];
    sf[(32 + r) * 4 + s] = f3;
    const float nm4[15] = {1, 4, 6, 4, 1, 4, 12, 12, 4, 6, 12, 6, 4, 4, 1};
    float f4 = 0.f;
#pragma unroll
    for (int c = 0; c < 15; c++) f4 += nm4[c] * acc[20 + c] * acc[20 + c];
    sf[(40 + r) * 4 + s] = f4;
    __syncthreads();

    // ---- CTA-batched MLP: thread owns neuron j for the 2 atoms of its warp pair ----
    int j = t & 63, g2i = t >> 6;           // warp pair g2i covers atoms 2*g2i, 2*g2i+1
    int a0 = 2 * g2i, a1 = a0 + 1;

    // layer 1: 192 -> 64 (W1 rows read coalesced, shared by both atoms)
    float h0 = sB1[j], h1 = sB1[j];
    const float4* fa4 = (const float4*)sfeat[a0];
    const float4* fb4 = (const float4*)sfeat[a1];
#pragma unroll 4
    for (int f4i = 0; f4i < 48; f4i++) {
        float4 qa = fa4[f4i], qb = fb4[f4i];
        int fb = f4i * 4;
        float w0 = __ldg(&Wa1[(fb + 0) * 64 + j]);
        float w1 = __ldg(&Wa1[(fb + 1) * 64 + j]);
        float w2 = __ldg(&Wa1[(fb + 2) * 64 + j]);
        float w3 = __ldg(&Wa1[(fb + 3) * 64 + j]);
        h0 = fmaf(qa.x, w0, h0); h1 = fmaf(qb.x, w0, h1);
        h0 = fmaf(qa.y, w1, h0); h1 = fmaf(qb.y, w1, h1);
        h0 = fmaf(qa.z, w2, h0); h1 = fmaf(qb.z, w2, h1);
        h0 = fmaf(qa.w, w3, h0); h1 = fmaf(qb.w, w3, h1);
    }
    sh1[a0][j] = silu(h0);
    sh1[a1][j] = silu(h1);
    __syncthreads();

    // layer 2: 64 -> 64 (all from smem)
    float g0 = sB2[j], g1 = sB2[j];
    const float4* ha4 = (const float4*)sh1[a0];
    const float4* hb4 = (const float4*)sh1[a1];
#pragma unroll 4
    for (int k4 = 0; k4 < 16; k4++) {
        float4 qa = ha4[k4], qb = hb4[k4];
        int kb = k4 * 4;
        float w0 = sW2[(kb + 0) * 64 + j];
        float w1 = sW2[(kb + 1) * 64 + j];
        float w2 = sW2[(kb + 2) * 64 + j];
        float w3 = sW2[(kb + 3) * 64 + j];
        g0 = fmaf(qa.x, w0, g0); g1 = fmaf(qb.x, w0, g1);
        g0 = fmaf(qa.y, w1, g0); g1 = fmaf(qb.y, w1, g1);
        g0 = fmaf(qa.z, w2, g0); g1 = fmaf(qb.z, w2, g1);
        g0 = fmaf(qa.w, w3, g0); g1 = fmaf(qb.w, w3, g1);
    }
    float w3j = sW3[j];
    float p0 = silu(g0) * w3j, p1 = silu(g1) * w3j;
#pragma unroll
    for (int off = 16; off; off >>= 1) {
        p0 += __shfl_down_sync(0xffffffffu, p0, off);
        p1 += __shfl_down_sync(0xffffffffu, p1, off);
    }
    if (lane == 0) { spart[warp][0] = p0; spart[warp][1] = p1; }
    __syncthreads();
    if (t < 8)
        out[blockIdx.x * 8 + t] = spart[2 * (t >> 1)][t & 1]
                                + spart[2 * (t >> 1) + 1][t & 1] + ba3[0];
}

extern "C" void kernel_launch(void* const* d_in, const int* in_sizes, int n_in,
                              void* d_out, int out_size) {
    const float* rij = (const float*)d_in[0];
    const int* species = (const int*)d_in[1];
    const int* fa = (const int*)d_in[2];
    const int* sa = (const int*)d_in[3];
    const float* Wr1 = (const float*)d_in[4];
    const float* br1 = (const float*)d_in[5];
    const float* Wr2 = (const float*)d_in[6];
    const float* br2 = (const float*)d_in[7];
    const float* Ws1 = (const float*)d_in[8];
    const float* bs1 = (const float*)d_in[9];
    const float* Ws2 = (const float*)d_in[10];
    const float* bs2 = (const float*)d_in[11];
    const float* Wa1 = (const float*)d_in[12];
    const float* ba1 = (const float*)d_in[13];
    const float* Wa2 = (const float*)d_in[14];
    const float* ba2 = (const float*)d_in[15];
    const float* Wa3 = (const float*)d_in[16];
    const float* ba3 = (const float*)d_in[17];
    float* out = (float*)d_out;

    k_edge_tbl<<<EDGE_BLOCKS + TBL_BLOCKS, 128>>>(rij, species, fa, sa,
                                                  Wr1, br1, Wr2, br2);
    k_atom_mlp<<<NA / 8, 256>>>(Wa1, ba1, Wa2, ba2, Wa3, ba3,
                                Ws1, bs1, Ws2, bs2, out);
}